// round 11
// baseline (speedup 1.0000x reference)
#include <cuda_runtime.h>
#include <math.h>

#define BB 16
#define HH 512
#define WW 512
#define WORDS_PER_ROW 16   // 512 / 32
#define NBLK (BB * 16 * 16)  // 4096 fused_edt blocks

// Scratch (no cudaMalloc allowed)
__device__ unsigned g_bits[BB * HH * WORDS_PER_ROW];  // 512 KB bitmask of gt!=0
__device__ float g_partial[NBLK];                     // per-tile partials
__device__ unsigned g_count;                          // last-block ticket (0-init)

// ---------------------------------------------------------------------------
// Kernel 1: pack gt (int32) -> bitmask. One thread per output BYTE (8 px):
// two int4 loads, register packing, single coalesced byte store.
// 524288 threads / 2048 blocks -> latency hidden by warp count.
// ---------------------------------------------------------------------------
__global__ void pack_bits(const int4* __restrict__ gt4) {
    int t = blockIdx.x * blockDim.x + threadIdx.x;   // one thread per 8 pixels
    int4 a = gt4[2 * t];
    int4 c = gt4[2 * t + 1];
    unsigned byte = (a.x != 0 ? 1u : 0u)  | (a.y != 0 ? 2u : 0u)
                  | (a.z != 0 ? 4u : 0u)  | (a.w != 0 ? 8u : 0u)
                  | (c.x != 0 ? 16u : 0u) | (c.y != 0 ? 32u : 0u)
                  | (c.z != 0 ? 64u : 0u) | (c.w != 0 ? 128u : 0u);
    ((unsigned char*)g_bits)[t] = (unsigned char)byte;
}

// ---------------------------------------------------------------------------
// Exact global fallback: scan full-image bitmask with distance pruning.
// Reachable only when no fg within Chebyshev radius 16 — correctness insurance.
// ---------------------------------------------------------------------------
__device__ __noinline__ float global_fallback(int b, int gi, int gj, float best) {
    const unsigned* base = g_bits + ((size_t)b * HH * WORDS_PER_ROW);
    for (int dd = 0; dd < HH; ++dd) {
        float dd2 = (float)(dd * dd);
        if (dd2 >= best) break;
        for (int sgn = 0; sgn < 2; ++sgn) {
            if (sgn && dd == 0) continue;
            int r = sgn ? gi + dd : gi - dd;
            if (r < 0 || r >= HH) continue;
            const unsigned* row = base + r * WORDS_PER_ROW;
            for (int w = 0; w < WORDS_PER_ROW; ++w) {
                unsigned word = row[w];
                while (word) {
                    int bit = __ffs(word) - 1;
                    word &= word - 1;
                    float dj = (float)((w << 5) + bit - gj);
                    best = fminf(best, dd2 + dj * dj);
                }
            }
        }
    }
    return best;
}

// ---------------------------------------------------------------------------
// Cold path: exact expanding-Chebyshev-ring search from r=3 (5x5 was empty).
// ---------------------------------------------------------------------------
__device__ __noinline__ float ring_search(const unsigned long long* s,
                                          int li, int lj, int b, int gi, int gj) {
    float best = 1e30f;
    for (int r = 3; r <= 16; ++r) {
        float rr = (float)(r * r);
        if (rr >= best) break;
        int sh = lj - r;                       // >= 0 (lj >= 16)
        unsigned long long m = (s[li - r] | s[li + r]) >> sh;
        m &= (1ull << (2 * r + 1)) - 1ull;     // width <= 33 bits
        if (m) {
            unsigned long long right = m >> r;                         // dj >= 0
            unsigned long long left  = m & ((1ull << (r + 1)) - 1ull); // dj <= 0
            int dj = 64;
            if (right) dj = __ffsll((long long)right) - 1;
            if (left) {
                int pp = 63 - __clzll((long long)left);
                int dl = r - pp;
                dj = dj < dl ? dj : dl;
            }
            best = fminf(best, rr + (float)(dj * dj));
        }
        if (rr < best) {
            int shl = lj - r, shr = lj + r;    // shr <= 63
            for (int di = 0; di < r; ++di) {
                unsigned long long ra = s[li - di] | s[li + di];
                if (((ra >> shl) | (ra >> shr)) & 1ull) {
                    best = fminf(best, rr + (float)(di * di));
                    break;
                }
            }
        }
    }
    if (best > 289.0f)
        best = global_fallback(b, gi, gj, best);
    return best;
}

// ---------------------------------------------------------------------------
// Kernel 2: fused exact EDT + sqrt + probs multiply + reduction (all of it).
// Thread = 4 CONSECUTIVE COLUMNS in one row -> probs is one float4 load;
// window shifts: 5 x 64-bit row extracts (8-bit fields), per-pixel >>k.
// Hot path: branchless 5x5 classifier (d^2 in {0,1,2,4,5,8}); cold path
// (P = 2^-25 per pixel) -> exact ring search -> exact global fallback.
// Last finishing block reduces all 4096 partials (deterministic fixed order).
// Grid: (W/32, H/32, B); block 256.
// ---------------------------------------------------------------------------
__global__ void fused_edt(const float* __restrict__ probs,
                          float* __restrict__ out) {
    __shared__ unsigned long long s[64];
    __shared__ float wsum[8];
    __shared__ int is_last;

    int b   = blockIdx.z;
    int ti0 = blockIdx.y * 32;
    int tj0 = blockIdx.x * 32;
    int tid = threadIdx.x;

    // Load 64-row x 64-bit window; outside-image = 0 (no fg).
    // Bit l of s[row] = global column (tj0 - 16 + l).
    if (tid < 64) {
        int gi = ti0 - 16 + tid;
        unsigned long long v = 0ull;
        if (gi >= 0 && gi < HH) {
            const unsigned* bp = g_bits + ((size_t)(b * HH + gi)) * WORDS_PER_ROW;
            int w0 = tj0 >> 5;
            unsigned m1 = (w0 > 0)                 ? bp[w0 - 1] : 0u;
            unsigned c0 = bp[w0];
            unsigned p1 = (w0 < WORDS_PER_ROW - 1) ? bp[w0 + 1] : 0u;
            v = ((unsigned long long)m1 >> 16)
              | ((unsigned long long)c0 << 16)
              | ((unsigned long long)p1 << 48);
        }
        s[tid] = v;
    }
    __syncthreads();

    int gcol = tid & 7;                // column group (4 cols each)
    int ti   = tid >> 3;               // row within tile, 0..31
    int li   = 16 + ti;                // local row
    int lj0  = 16 + gcol * 4;          // local col of pixel k=0, in [16, 44]
    int sh   = lj0 - 2;                // in [14, 42]

    // 5 window rows -> 8-bit fields (bit i = column offset i-2 from pixel k=0)
    unsigned r8[5];
    #pragma unroll
    for (int m = 0; m < 5; ++m)
        r8[m] = (unsigned)(s[li - 2 + m] >> sh) & 0xFFu;
    unsigned c1r = r8[1] | r8[3];      // rows +-1
    unsigned c2r = r8[0] | r8[4];      // rows +-2

    // probs layout [B, 2, H, W] channel 0; 16B-aligned float4.
    const float4 p4 = *(const float4*)&probs[(((size_t)b * 2) * HH + (ti0 + ti)) * WW
                                             + (tj0 + gcol * 4)];
    float pv[4] = {p4.x, p4.y, p4.z, p4.w};

    float acc = 0.0f;
    #pragma unroll
    for (int k = 0; k < 4; ++k) {
        unsigned a5 = (r8[2] >> k) & 31u;
        unsigned c1 = (c1r  >> k) & 31u;
        unsigned c2 = (c2r  >> k) & 31u;

        unsigned h0 = a5 & 0x4u;                              // d^2 = 0
        unsigned h1 = (a5 & 0xAu)  | (c1 & 0x4u);             // d^2 = 1
        unsigned h2 = c1 & 0xAu;                              // d^2 = 2
        unsigned h4 = (a5 & 0x11u) | (c2 & 0x4u);             // d^2 = 4
        unsigned h5 = (c1 & 0x11u) | (c2 & 0xAu);             // d^2 = 5
        unsigned h8 = c2 & 0x11u;                             // d^2 = 8

        float dist;
        if (h0 | h1 | h2 | h4 | h5 | h8) {
            dist = h0 ? 0.0f
                 : h1 ? 1.0f
                 : h2 ? 1.41421356237309515f    // sqrt(2)
                 : h4 ? 2.0f
                 : h5 ? 2.23606797749978981f    // sqrt(5)
                 :      2.82842712474619029f;   // sqrt(8)
        } else {
            int lj = lj0 + k;
            dist = sqrtf(ring_search(s, li, lj, b, ti0 + ti, tj0 + gcol * 4 + k));
        }
        acc += dist * pv[k];
    }

    // deterministic block reduction (8 warps)
    #pragma unroll
    for (int off = 16; off > 0; off >>= 1)
        acc += __shfl_down_sync(0xffffffffu, acc, off);
    if ((tid & 31) == 0) wsum[tid >> 5] = acc;
    __syncthreads();
    if (tid < 8) {
        float v = wsum[tid];
        #pragma unroll
        for (int off = 4; off > 0; off >>= 1)
            v += __shfl_down_sync(0x000000ffu, v, off);
        if (tid == 0) {
            g_partial[(blockIdx.z * 16 + blockIdx.y) * 16 + blockIdx.x] = v;
            __threadfence();
            unsigned ticket = atomicAdd(&g_count, 1u);
            is_last = (ticket == NBLK - 1);
        }
    }
    __syncthreads();

    // Last block reduces all partials in a fixed order (deterministic).
    if (is_last) {
        __threadfence();
        float v = 0.0f;
        for (int k = tid; k < NBLK; k += 256) v += g_partial[k];
        #pragma unroll
        for (int off = 16; off > 0; off >>= 1)
            v += __shfl_down_sync(0xffffffffu, v, off);
        if ((tid & 31) == 0) wsum[tid >> 5] = v;
        __syncthreads();
        if (tid < 8) {
            float w = wsum[tid];
            #pragma unroll
            for (int off = 4; off > 0; off >>= 1)
                w += __shfl_down_sync(0x000000ffu, w, off);
            if (tid == 0) {
                out[0] = w * (1.0f / (float)((size_t)BB * HH * WW));
                g_count = 0;   // self-reset for graph replay
            }
        }
    }
}

extern "C" void kernel_launch(void* const* d_in, const int* in_sizes, int n_in,
                              void* d_out, int out_size) {
    const float* probs = (const float*)d_in[0];
    const int*   gt    = (const int*)d_in[1];
    float* out = (float*)d_out;

    // one thread per 8 pixels: 4194304 / 8 / 256 = 2048 blocks
    pack_bits<<<2048, 256>>>((const int4*)gt);
    dim3 grid(WW / 32, HH / 32, BB);
    fused_edt<<<grid, 256>>>(probs, out);
}